// round 2
// baseline (speedup 1.0000x reference)
#include <cuda_runtime.h>
#include <cstdint>

// Problem constants (fixed shapes per reference)
#define Dn    128
#define Nn    100000
#define En    50000
#define Cn    2000
#define NNZn  1600000
#define ETn   (En + Nn)        // 150000 edges incl. self-loop edges
#define NNZTn (NNZn + Nn)      // 1700000 incidences incl. self-loops

// ---------------- static device scratch (no allocations allowed) ----------------
__device__ float g_t[(size_t)ETn * Dn];   // transformed features (reused)
__device__ float g_e[(size_t)ETn * Dn];   // edge accumulators / edge features (raw sums)
__device__ float g_n[(size_t)Nn  * Dn];   // node accumulators (raw sums)
__device__ float g_cA[Cn * Dn];           // component sums from edges
__device__ float g_cB[Cn * Dn];           // component sums from nodes
__device__ int   g_dege[ETn];
__device__ int   g_degn[Nn];
__device__ int   g_cce[Cn];
__device__ int   g_ccn[Cn];

// ---------------- helpers ----------------
__device__ __forceinline__ void red_add_v4(float* addr, float4 v) {
    asm volatile("red.global.add.v4.f32 [%0], {%1, %2, %3, %4};"
                 :: "l"(addr), "f"(v.x), "f"(v.y), "f"(v.z), "f"(v.w) : "memory");
}

__device__ __forceinline__ float prelu_f(float x, float a) { return x >= 0.f ? x : a * x; }

// ---------------- degree / count kernels ----------------
__global__ void count_deg_kernel(const int* __restrict__ hidx,
                                 int* __restrict__ dege, int* __restrict__ degn) {
    int i = blockIdx.x * blockDim.x + threadIdx.x;
    if (i >= NNZTn) return;
    int s, d;
    if (i < NNZn) { s = hidx[i]; d = hidx[NNZn + i]; }
    else          { s = i - NNZn; d = En + s; }
    atomicAdd(&dege[d], 1);
    atomicAdd(&degn[s], 1);
}

__global__ void count_comp_kernel(const int* __restrict__ ci, int* __restrict__ cnt, int M) {
    int i = blockIdx.x * blockDim.x + threadIdx.x;
    if (i >= M) return;
    atomicAdd(&cnt[ci[i]], 1);
}

// ---------------- GEMM: Out[M x 128] = f(A) @ W + b ----------------
// f(A) row-wise: optionally scale by 1/max(cnt,1), optionally PReLU.
// Block: 256 threads, 32 rows per block. W tiled 64 rows of K at a time in smem.
// Thread t computes row rb + (t>>3), cols { (t&7)*4 + 32*g + u : g,u in 0..3 }  (conflict-free LDS.128)
__global__ __launch_bounds__(256)
void gemm_kernel(const float* __restrict__ A, const int* __restrict__ rowcnt,
                 int doPrelu, const float* __restrict__ pa,
                 const float* __restrict__ W, const float* __restrict__ bias,
                 float* __restrict__ Out, int M)
{
    __shared__ float Ws[64 * Dn];       // 32 KB
    __shared__ float As[32 * 68];       // padded rows (68 floats), 8.5 KB

    const int tid  = threadIdx.x;
    const int rloc = tid >> 3;          // 0..31
    const int cb   = (tid & 7) * 4;     // 0,4,...,28
    const int rb   = blockIdx.x * 32;
    const float aneg = __ldg(pa);

    float acc[16];
#pragma unroll
    for (int j = 0; j < 16; j++) acc[j] = 0.f;

    for (int kt = 0; kt < 2; kt++) {
        // load W tile (64 x 128) linearly
        const float4* Wv  = (const float4*)(W + (size_t)kt * 64 * Dn);
        float4*       Wsv = (float4*)Ws;
#pragma unroll
        for (int q = 0; q < 8; q++) Wsv[tid + q * 256] = Wv[tid + q * 256];

        // load A tile (32 rows x 64 cols) with row transform
#pragma unroll
        for (int q = 0; q < 2; q++) {
            int f4  = tid + q * 256;          // 0..511
            int r   = f4 >> 4;                // row in tile
            int cc  = (f4 & 15) * 4;          // col in tile (float)
            int grow = rb + r;
            float4 v = make_float4(0.f, 0.f, 0.f, 0.f);
            if (grow < M) {
                v = *(const float4*)(A + (size_t)grow * Dn + kt * 64 + cc);
                if (rowcnt) {
                    int c = rowcnt[grow];
                    float s = 1.f / (float)(c > 1 ? c : 1);
                    v.x *= s; v.y *= s; v.z *= s; v.w *= s;
                }
                if (doPrelu) {
                    v.x = prelu_f(v.x, aneg); v.y = prelu_f(v.y, aneg);
                    v.z = prelu_f(v.z, aneg); v.w = prelu_f(v.w, aneg);
                }
            }
            *(float4*)(As + r * 68 + cc) = v;
        }
        __syncthreads();

        const float* asr = As + rloc * 68;
#pragma unroll 16
        for (int k = 0; k < 64; k++) {
            float a = asr[k];
            const float4* wr = (const float4*)(Ws + k * Dn);
#pragma unroll
            for (int g = 0; g < 4; g++) {
                float4 w = wr[(cb >> 2) + 8 * g];
                acc[g * 4 + 0] += a * w.x;
                acc[g * 4 + 1] += a * w.y;
                acc[g * 4 + 2] += a * w.z;
                acc[g * 4 + 3] += a * w.w;
            }
        }
        __syncthreads();
    }

    int grow = rb + rloc;
    if (grow < M) {
#pragma unroll
        for (int g = 0; g < 4; g++) {
            int col = cb + 32 * g;
            float4 b4 = *(const float4*)(bias + col);
            float4 o;
            o.x = acc[g * 4 + 0] + b4.x;
            o.y = acc[g * 4 + 1] + b4.y;
            o.z = acc[g * 4 + 2] + b4.z;
            o.w = acc[g * 4 + 3] + b4.w;
            *(float4*)(Out + (size_t)grow * Dn + col) = o;
        }
    }
}

// ---------------- incidence scatter: 32 float4-lanes per incidence ----------------
// e2v==0: Acc[dst] += T[src]   (node->edge)
// e2v==1: Acc[src] += T[dst]   (edge->node)
__global__ void scatter_incidence_kernel(const float* __restrict__ T,
                                         const int* __restrict__ hidx,
                                         float* __restrict__ Acc, int e2v)
{
    long long idx = (long long)blockIdx.x * blockDim.x + threadIdx.x;
    if (idx >= (long long)NNZTn * 32) return;
    int i  = (int)(idx >> 5);
    int ch = ((int)idx & 31) << 2;
    int s, d;
    if (i < NNZn) { s = hidx[i]; d = hidx[NNZn + i]; }
    else          { s = i - NNZn; d = En + s; }
    int gs = e2v ? d : s;
    int gd = e2v ? s : d;
    float4 v = *(const float4*)(T + (size_t)gs * Dn + ch);
    red_add_v4(Acc + (size_t)gd * Dn + ch, v);
}

// ---------------- component scatter ----------------
__global__ void scatter_comp_kernel(const float* __restrict__ T,
                                    const int* __restrict__ gi, const int* __restrict__ si,
                                    float* __restrict__ Cb, int M)
{
    long long idx = (long long)blockIdx.x * blockDim.x + threadIdx.x;
    if (idx >= (long long)M * 32) return;
    int j  = (int)(idx >> 5);
    int ch = ((int)idx & 31) << 2;
    float4 v = *(const float4*)(T + (size_t)gi[j] * Dn + ch);
    red_add_v4(Cb + (size_t)si[j] * Dn + ch, v);
}

// ---------------- output kernels ----------------
__global__ void out_rows_kernel(const float* __restrict__ buf, const int* __restrict__ cnt,
                                const float* __restrict__ pa, float* __restrict__ out, int M)
{
    long long idx = (long long)blockIdx.x * blockDim.x + threadIdx.x;
    if (idx >= (long long)M * 32) return;
    int r  = (int)(idx >> 5);
    int ch = ((int)idx & 31) << 2;
    int c = cnt[r];
    float inv = 1.f / (float)(c > 1 ? c : 1);
    float a = __ldg(pa);
    float4 v = *(const float4*)(buf + (size_t)r * Dn + ch);
    v.x = prelu_f(v.x * inv, a); v.y = prelu_f(v.y * inv, a);
    v.z = prelu_f(v.z * inv, a); v.w = prelu_f(v.w * inv, a);
    *(float4*)(out + (size_t)r * Dn + ch) = v;
}

__global__ void out_comp_kernel(const float* __restrict__ cA, const float* __restrict__ cB,
                                const int* __restrict__ cce, const int* __restrict__ ccn,
                                const float* __restrict__ pa, float* __restrict__ out)
{
    long long idx = (long long)blockIdx.x * blockDim.x + threadIdx.x;
    if (idx >= (long long)Cn * 32) return;
    int c  = (int)(idx >> 5);
    int ch = ((int)idx & 31) << 2;
    int ca = cce[c], cb = ccn[c];
    float ia = 1.f / (float)(ca > 1 ? ca : 1);
    float ib = 1.f / (float)(cb > 1 ? cb : 1);
    float a = __ldg(pa);
    float4 va = *(const float4*)(cA + (size_t)c * Dn + ch);
    float4 vb = *(const float4*)(cB + (size_t)c * Dn + ch);
    float4 o;
    o.x = prelu_f(va.x * ia + vb.x * ib, a);
    o.y = prelu_f(va.y * ia + vb.y * ib, a);
    o.z = prelu_f(va.z * ia + vb.z * ib, a);
    o.w = prelu_f(va.w * ia + vb.w * ib, a);
    *(float4*)(out + (size_t)c * Dn + ch) = o;
}

// ---------------- host launch ----------------
static inline int cdiv(long long a, int b) { return (int)((a + b - 1) / b); }

extern "C" void kernel_launch(void* const* d_in, const int* in_sizes, int n_in,
                              void* d_out, int out_size)
{
    const float* x    = (const float*)d_in[0];
    const int*   hidx = (const int*)  d_in[1];   // [2, NNZ]: row0 src(node), row1 dst(edge)
    const int*   hc   = (const int*)  d_in[2];   // [2, E]:   row0 edge idx, row1 comp idx
    const int*   nc   = (const int*)  d_in[3];   // [2, N]
    const float* pa   = (const float*)d_in[7];
    const float* Wv0 = (const float*)d_in[8];   const float* bv0 = (const float*)d_in[9];
    const float* We0 = (const float*)d_in[10];  const float* be0 = (const float*)d_in[11];
    // d_in[12..15] = W_e2c_0 / b / W_n2c_0 / b  -- dead (layer-0 c is discarded)
    const float* Wv1 = (const float*)d_in[16];  const float* bv1 = (const float*)d_in[17];
    const float* We1 = (const float*)d_in[18];  const float* be1 = (const float*)d_in[19];
    const float* Wec1= (const float*)d_in[20];  const float* bec1= (const float*)d_in[21];
    const float* Wnc1= (const float*)d_in[22];  const float* bnc1= (const float*)d_in[23];

    float *t, *e, *nb, *cA, *cB;
    int *dege, *degn, *cce, *ccn;
    cudaGetSymbolAddress((void**)&t,    g_t);
    cudaGetSymbolAddress((void**)&e,    g_e);
    cudaGetSymbolAddress((void**)&nb,   g_n);
    cudaGetSymbolAddress((void**)&cA,   g_cA);
    cudaGetSymbolAddress((void**)&cB,   g_cB);
    cudaGetSymbolAddress((void**)&dege, g_dege);
    cudaGetSymbolAddress((void**)&degn, g_degn);
    cudaGetSymbolAddress((void**)&cce,  g_cce);
    cudaGetSymbolAddress((void**)&ccn,  g_ccn);

    const int TB = 256;
    const int gInc  = cdiv((long long)NNZTn * 32, TB);
    const int gE    = cdiv((long long)ETn  * 32, TB);
    const int gN32  = cdiv((long long)Nn   * 32, TB);
    const int gE32  = cdiv((long long)En   * 32, TB);
    const int gC32  = cdiv((long long)Cn   * 32, TB);

    // ---- degrees / counts (same for both layers) ----
    cudaMemsetAsync(dege, 0, ETn * sizeof(int), 0);
    cudaMemsetAsync(degn, 0, Nn  * sizeof(int), 0);
    cudaMemsetAsync(cce,  0, Cn  * sizeof(int), 0);
    cudaMemsetAsync(ccn,  0, Cn  * sizeof(int), 0);
    count_deg_kernel<<<cdiv(NNZTn, TB), TB>>>(hidx, dege, degn);
    count_comp_kernel<<<cdiv(En, TB), TB>>>(hc + En, cce, En);
    count_comp_kernel<<<cdiv(Nn, TB), TB>>>(nc + Nn, ccn, Nn);

    // ================= layer 0 =================
    // t1 = x @ Wv0 + bv0
    gemm_kernel<<<cdiv(Nn, 32), TB>>>(x, nullptr, 0, pa, Wv0, bv0, t, Nn);
    cudaMemsetAsync(e, 0, (size_t)ETn * Dn * sizeof(float), 0);
    scatter_incidence_kernel<<<gInc, TB>>>(t, hidx, e, 0);
    // t2 = prelu(mean_e) @ We0 + be0
    gemm_kernel<<<cdiv(ETn, 32), TB>>>(e, dege, 1, pa, We0, be0, t, ETn);
    cudaMemsetAsync(nb, 0, (size_t)Nn * Dn * sizeof(float), 0);
    scatter_incidence_kernel<<<gInc, TB>>>(t, hidx, nb, 1);
    // nb now holds raw node sums of layer-0 n; mean+prelu fused into next GEMM read

    // ================= layer 1 =================
    // h = prelu(mean(n0)); t1 = h @ Wv1 + bv1
    gemm_kernel<<<cdiv(Nn, 32), TB>>>(nb, degn, 1, pa, Wv1, bv1, t, Nn);
    cudaMemsetAsync(e, 0, (size_t)ETn * Dn * sizeof(float), 0);
    scatter_incidence_kernel<<<gInc, TB>>>(t, hidx, e, 0);
    // t2 = prelu(mean_e1) @ We1 + be1
    gemm_kernel<<<cdiv(ETn, 32), TB>>>(e, dege, 1, pa, We1, be1, t, ETn);
    cudaMemsetAsync(nb, 0, (size_t)Nn * Dn * sizeof(float), 0);
    scatter_incidence_kernel<<<gInc, TB>>>(t, hidx, nb, 1);
    // nb = raw sums of layer-1 n

    // e2c: t3 = prelu(mean_e1)[0:E] @ Wec1 + bec1 ; scatter-mean by component
    gemm_kernel<<<cdiv(En, 32), TB>>>(e, dege, 1, pa, Wec1, bec1, t, En);
    cudaMemsetAsync(cA, 0, (size_t)Cn * Dn * sizeof(float), 0);
    scatter_comp_kernel<<<gE32, TB>>>(t, hc, hc + En, cA, En);

    // n2c: t4 = mean(n1) @ Wnc1 + bnc1 ; scatter-mean by component
    gemm_kernel<<<cdiv(Nn, 32), TB>>>(nb, degn, 0, pa, Wnc1, bnc1, t, Nn);
    cudaMemsetAsync(cB, 0, (size_t)Cn * Dn * sizeof(float), 0);
    scatter_comp_kernel<<<gN32, TB>>>(t, nc, nc + Nn, cB, Nn);

    // ================= outputs =================
    float* out = (float*)d_out;
    out_rows_kernel<<<gN32, TB>>>(nb, degn, pa, out, Nn);                          // prelu(n1)
    out_rows_kernel<<<gE32, TB>>>(e, dege, pa, out + (size_t)Nn * Dn, En);         // e1[:E]
    out_comp_kernel<<<gC32, TB>>>(cA, cB, cce, ccn, pa, out + (size_t)(Nn + En) * Dn);
    (void)in_sizes; (void)n_in; (void)out_size;
}

// round 3
// speedup vs baseline: 1.5317x; 1.5317x over previous
#include <cuda_runtime.h>
#include <cstdint>

// Problem constants (fixed shapes per reference)
#define Dn    128
#define Nn    100000
#define En    50000
#define Cn    2000
#define NNZn  1600000
#define ETn   (En + Nn)        // 150000 edges incl. self-loop edges
#define NNZTn (NNZn + Nn)      // 1700000 incidences incl. self-loops

// ---------------- static device scratch (no allocations allowed) ----------------
__device__ float g_t [(size_t)ETn * Dn];  // transformed node features (v2e output)
__device__ float g_e [(size_t)ETn * Dn];  // edge raw sums
__device__ float g_a [(size_t)Nn  * Dn];  // node raw sums (edge->node aggregation)
__device__ float g_nf[(size_t)Nn  * Dn];  // node features n (post e2v GEMM, pre-prelu)
__device__ float g_cA[Cn * Dn];           // component raw sums from edges
__device__ float g_cB[Cn * Dn];           // component raw sums from nodes
__device__ float g_cEo[Cn * Dn];          // component GEMM out (edge branch)
__device__ float g_cNo[Cn * Dn];          // component GEMM out (node branch)
__device__ int   g_dege[ETn];
__device__ int   g_degn[Nn];
__device__ int   g_cce[Cn];
__device__ int   g_ccn[Cn];

// ---------------- helpers ----------------
__device__ __forceinline__ void red_add_v4(float* addr, float4 v) {
    asm volatile("red.global.add.v4.f32 [%0], {%1, %2, %3, %4};"
                 :: "l"(addr), "f"(v.x), "f"(v.y), "f"(v.z), "f"(v.w) : "memory");
}
__device__ __forceinline__ float prelu_f(float x, float a) { return x >= 0.f ? x : a * x; }

// ---------------- degree / count kernels ----------------
__global__ void count_deg_kernel(const int* __restrict__ hidx,
                                 int* __restrict__ dege, int* __restrict__ degn) {
    int i = blockIdx.x * blockDim.x + threadIdx.x;
    if (i >= NNZTn) return;
    int s, d;
    if (i < NNZn) { s = hidx[i]; d = hidx[NNZn + i]; }
    else          { s = i - NNZn; d = En + s; }
    atomicAdd(&dege[d], 1);
    atomicAdd(&degn[s], 1);
}

__global__ void count_comp_kernel(const int* __restrict__ ci, int* __restrict__ cnt, int M) {
    int i = blockIdx.x * blockDim.x + threadIdx.x;
    if (i >= M) return;
    atomicAdd(&cnt[ci[i]], 1);
}

// ---------------- SGEMM: Out[M x 128] = f(A) @ W + bias ----------------
// f(A) row-wise: scale by 1/max(rowcnt,1) if rowcnt != null, then optional PReLU.
// If Out2 != null, additionally writes Out2 = prelu(Out).
// 128x128 block tile, 256 threads, 8x8 micro-tile, BK=16, A transposed in smem.
__global__ __launch_bounds__(256, 2)
void sgemm128(const float* __restrict__ A, const int* __restrict__ rowcnt,
              int inPrelu, const float* __restrict__ pa,
              const float* __restrict__ W, const float* __restrict__ bias,
              float* __restrict__ Out, float* __restrict__ Out2, int M)
{
    __shared__ float As[16][132];   // [k][m], padded
    __shared__ float Bs[16][128];   // [k][n]

    const int tid = threadIdx.x;
    const int tx  = tid & 15;        // 0..15  (col group: cols tx*8 .. tx*8+7)
    const int ty  = tid >> 4;        // 0..15  (row group: rows ty*8 .. ty*8+7)
    const int rb  = blockIdx.x * 128;
    const float aneg = __ldg(pa);

    float acc[8][8];
#pragma unroll
    for (int i = 0; i < 8; i++)
#pragma unroll
        for (int j = 0; j < 8; j++) acc[i][j] = 0.f;

    for (int kb = 0; kb < 128; kb += 16) {
        // ---- load A tile (128 rows x 16 k), transform rows, store transposed ----
#pragma unroll
        for (int q = 0; q < 2; q++) {
            int lin = tid + q * 256;        // 0..511
            int r   = lin >> 2;             // 0..127
            int kc  = (lin & 3) << 2;       // 0,4,8,12
            int grow = rb + r;
            float4 v = make_float4(0.f, 0.f, 0.f, 0.f);
            if (grow < M) {
                v = *(const float4*)(A + (size_t)grow * Dn + kb + kc);
                if (rowcnt) {
                    int c = rowcnt[grow];
                    float s = 1.f / (float)(c > 1 ? c : 1);
                    v.x *= s; v.y *= s; v.z *= s; v.w *= s;
                }
                if (inPrelu) {
                    v.x = prelu_f(v.x, aneg); v.y = prelu_f(v.y, aneg);
                    v.z = prelu_f(v.z, aneg); v.w = prelu_f(v.w, aneg);
                }
            }
            As[kc + 0][r] = v.x; As[kc + 1][r] = v.y;
            As[kc + 2][r] = v.z; As[kc + 3][r] = v.w;
        }
        // ---- load B tile (16 k x 128 n) straight copy ----
#pragma unroll
        for (int q = 0; q < 2; q++) {
            int lin = tid + q * 256;
            int k   = lin >> 5;             // 0..15
            int nc  = (lin & 31) << 2;      // 0..124
            *(float4*)&Bs[k][nc] = *(const float4*)(W + (size_t)(kb + k) * Dn + nc);
        }
        __syncthreads();

#pragma unroll
        for (int k = 0; k < 16; k++) {
            float a[8], b[8];
            *(float4*)(a)     = *(float4*)&As[k][ty * 8];
            *(float4*)(a + 4) = *(float4*)&As[k][ty * 8 + 4];
            *(float4*)(b)     = *(float4*)&Bs[k][tx * 8];
            *(float4*)(b + 4) = *(float4*)&Bs[k][tx * 8 + 4];
#pragma unroll
            for (int i = 0; i < 8; i++)
#pragma unroll
                for (int j = 0; j < 8; j++)
                    acc[i][j] += a[i] * b[j];
        }
        __syncthreads();
    }

    // ---- epilogue: bias, store (and optional prelu copy) ----
    float bc[8];
    *(float4*)(bc)     = *(const float4*)(bias + tx * 8);
    *(float4*)(bc + 4) = *(const float4*)(bias + tx * 8 + 4);
#pragma unroll
    for (int i = 0; i < 8; i++) {
        int grow = rb + ty * 8 + i;
        if (grow < M) {
            float o[8];
#pragma unroll
            for (int j = 0; j < 8; j++) o[j] = acc[i][j] + bc[j];
            float* dst = Out + (size_t)grow * Dn + tx * 8;
            *(float4*)(dst)     = *(float4*)(o);
            *(float4*)(dst + 4) = *(float4*)(o + 4);
            if (Out2) {
                float p[8];
#pragma unroll
                for (int j = 0; j < 8; j++) p[j] = prelu_f(o[j], aneg);
                float* d2 = Out2 + (size_t)grow * Dn + tx * 8;
                *(float4*)(d2)     = *(float4*)(p);
                *(float4*)(d2 + 4) = *(float4*)(p + 4);
            }
        }
    }
}

// ---------------- v2e scatter: Eraw[dst] += T[src] ----------------
__global__ void scatter_v2e_kernel(const float* __restrict__ T,
                                   const int* __restrict__ hidx,
                                   float* __restrict__ Eraw)
{
    long long idx = (long long)blockIdx.x * blockDim.x + threadIdx.x;
    if (idx >= (long long)NNZTn * 32) return;
    int i  = (int)(idx >> 5);
    int ch = ((int)idx & 31) << 2;
    int s, d;
    if (i < NNZn) { s = hidx[i]; d = hidx[NNZn + i]; }
    else          { s = i - NNZn; d = En + s; }
    float4 v = *(const float4*)(T + (size_t)s * Dn + ch);
    red_add_v4(Eraw + (size_t)d * Dn + ch, v);
}

// ---------------- e2n scatter: Nacc[src] += prelu(Eraw[dst]/dege[dst]) ----------------
__global__ void scatter_e2n_kernel(const float* __restrict__ Eraw,
                                   const int* __restrict__ hidx,
                                   const int* __restrict__ dege,
                                   const float* __restrict__ pa,
                                   float* __restrict__ Nacc)
{
    long long idx = (long long)blockIdx.x * blockDim.x + threadIdx.x;
    if (idx >= (long long)NNZTn * 32) return;
    int i  = (int)(idx >> 5);
    int ch = ((int)idx & 31) << 2;
    int s, d;
    if (i < NNZn) { s = hidx[i]; d = hidx[NNZn + i]; }
    else          { s = i - NNZn; d = En + s; }
    int c = dege[d];
    float inv = 1.f / (float)(c > 1 ? c : 1);
    float a = __ldg(pa);
    float4 v = *(const float4*)(Eraw + (size_t)d * Dn + ch);
    v.x = prelu_f(v.x * inv, a); v.y = prelu_f(v.y * inv, a);
    v.z = prelu_f(v.z * inv, a); v.w = prelu_f(v.w * inv, a);
    red_add_v4(Nacc + (size_t)s * Dn + ch, v);
}

// ---------------- e2c scatter: cAcc[he_c[j]] += prelu(Eraw[he_e[j]]/deg) ----------------
__global__ void scatter_e2c_kernel(const float* __restrict__ Eraw,
                                   const int* __restrict__ he_e,
                                   const int* __restrict__ he_c,
                                   const int* __restrict__ dege,
                                   const float* __restrict__ pa,
                                   float* __restrict__ cAcc)
{
    long long idx = (long long)blockIdx.x * blockDim.x + threadIdx.x;
    if (idx >= (long long)En * 32) return;
    int j  = (int)(idx >> 5);
    int ch = ((int)idx & 31) << 2;
    int eidx = he_e[j];
    int c = dege[eidx];
    float inv = 1.f / (float)(c > 1 ? c : 1);
    float a = __ldg(pa);
    float4 v = *(const float4*)(Eraw + (size_t)eidx * Dn + ch);
    v.x = prelu_f(v.x * inv, a); v.y = prelu_f(v.y * inv, a);
    v.z = prelu_f(v.z * inv, a); v.w = prelu_f(v.w * inv, a);
    red_add_v4(cAcc + (size_t)he_c[j] * Dn + ch, v);
}

// ---------------- n2c scatter: cAcc[nc_c[j]] += Nf[nc_n[j]] ----------------
__global__ void scatter_n2c_kernel(const float* __restrict__ Nf,
                                   const int* __restrict__ nc_n,
                                   const int* __restrict__ nc_c,
                                   float* __restrict__ cAcc)
{
    long long idx = (long long)blockIdx.x * blockDim.x + threadIdx.x;
    if (idx >= (long long)Nn * 32) return;
    int j  = (int)(idx >> 5);
    int ch = ((int)idx & 31) << 2;
    float4 v = *(const float4*)(Nf + (size_t)nc_n[j] * Dn + ch);
    red_add_v4(cAcc + (size_t)nc_c[j] * Dn + ch, v);
}

// ---------------- e output: prelu(Eraw/deg)[:E] ----------------
__global__ void out_e_kernel(const float* __restrict__ Eraw, const int* __restrict__ dege,
                             const float* __restrict__ pa, float* __restrict__ out)
{
    long long idx = (long long)blockIdx.x * blockDim.x + threadIdx.x;
    if (idx >= (long long)En * 32) return;
    int r  = (int)(idx >> 5);
    int ch = ((int)idx & 31) << 2;
    int c = dege[r];
    float inv = 1.f / (float)(c > 1 ? c : 1);
    float a = __ldg(pa);
    float4 v = *(const float4*)(Eraw + (size_t)r * Dn + ch);
    v.x = prelu_f(v.x * inv, a); v.y = prelu_f(v.y * inv, a);
    v.z = prelu_f(v.z * inv, a); v.w = prelu_f(v.w * inv, a);
    *(float4*)(out + (size_t)r * Dn + ch) = v;
}

// ---------------- component output: prelu(cE + cN) ----------------
__global__ void out_c_kernel(const float* __restrict__ cE, const float* __restrict__ cN,
                             const float* __restrict__ pa, float* __restrict__ out)
{
    long long idx = (long long)blockIdx.x * blockDim.x + threadIdx.x;
    if (idx >= (long long)Cn * 32) return;
    int r  = (int)(idx >> 5);
    int ch = ((int)idx & 31) << 2;
    float a = __ldg(pa);
    float4 va = *(const float4*)(cE + (size_t)r * Dn + ch);
    float4 vb = *(const float4*)(cN + (size_t)r * Dn + ch);
    float4 o;
    o.x = prelu_f(va.x + vb.x, a); o.y = prelu_f(va.y + vb.y, a);
    o.z = prelu_f(va.z + vb.z, a); o.w = prelu_f(va.w + vb.w, a);
    *(float4*)(out + (size_t)r * Dn + ch) = o;
}

// ---------------- host launch ----------------
static inline int cdiv(long long a, int b) { return (int)((a + b - 1) / b); }

extern "C" void kernel_launch(void* const* d_in, const int* in_sizes, int n_in,
                              void* d_out, int out_size)
{
    const float* x    = (const float*)d_in[0];
    const int*   hidx = (const int*)  d_in[1];   // [2, NNZ]: row0 src(node), row1 dst(edge)
    const int*   hc   = (const int*)  d_in[2];   // [2, E]:   row0 edge idx, row1 comp idx
    const int*   nc   = (const int*)  d_in[3];   // [2, N]
    const float* pa   = (const float*)d_in[7];
    const float* Wv0 = (const float*)d_in[8];   const float* bv0 = (const float*)d_in[9];
    const float* We0 = (const float*)d_in[10];  const float* be0 = (const float*)d_in[11];
    // d_in[12..15] = W_e2c_0 / b / W_n2c_0 / b  -- dead (layer-0 c is discarded)
    const float* Wv1 = (const float*)d_in[16];  const float* bv1 = (const float*)d_in[17];
    const float* We1 = (const float*)d_in[18];  const float* be1 = (const float*)d_in[19];
    const float* Wec1= (const float*)d_in[20];  const float* bec1= (const float*)d_in[21];
    const float* Wnc1= (const float*)d_in[22];  const float* bnc1= (const float*)d_in[23];

    float *t, *e, *aa, *nf, *cA, *cB, *cEo, *cNo;
    int *dege, *degn, *cce, *ccn;
    cudaGetSymbolAddress((void**)&t,    g_t);
    cudaGetSymbolAddress((void**)&e,    g_e);
    cudaGetSymbolAddress((void**)&aa,   g_a);
    cudaGetSymbolAddress((void**)&nf,   g_nf);
    cudaGetSymbolAddress((void**)&cA,   g_cA);
    cudaGetSymbolAddress((void**)&cB,   g_cB);
    cudaGetSymbolAddress((void**)&cEo,  g_cEo);
    cudaGetSymbolAddress((void**)&cNo,  g_cNo);
    cudaGetSymbolAddress((void**)&dege, g_dege);
    cudaGetSymbolAddress((void**)&degn, g_degn);
    cudaGetSymbolAddress((void**)&cce,  g_cce);
    cudaGetSymbolAddress((void**)&ccn,  g_ccn);

    const int TB = 256;
    const int gInc = cdiv((long long)NNZTn * 32, TB);
    const int gN32 = cdiv((long long)Nn * 32, TB);
    const int gE32 = cdiv((long long)En * 32, TB);
    const int gC32 = cdiv((long long)Cn * 32, TB);
    const int gmN  = cdiv(Nn, 128);
    const int gmC  = cdiv(Cn, 128);

    // ---- degrees / counts ----
    cudaMemsetAsync(dege, 0, ETn * sizeof(int), 0);
    cudaMemsetAsync(degn, 0, Nn  * sizeof(int), 0);
    cudaMemsetAsync(cce,  0, Cn  * sizeof(int), 0);
    cudaMemsetAsync(ccn,  0, Cn  * sizeof(int), 0);
    count_deg_kernel<<<cdiv(NNZTn, TB), TB>>>(hidx, dege, degn);
    count_comp_kernel<<<cdiv(En, TB), TB>>>(hc + En, cce, En);
    count_comp_kernel<<<cdiv(Nn, TB), TB>>>(nc + Nn, ccn, Nn);

    // ================= layer 0 =================
    // t = x @ Wv0 + bv0
    sgemm128<<<gmN, TB>>>(x, nullptr, 0, pa, Wv0, bv0, t, nullptr, Nn);
    cudaMemsetAsync(e, 0, (size_t)ETn * Dn * sizeof(float), 0);
    scatter_v2e_kernel<<<gInc, TB>>>(t, hidx, e);
    // aggregate prelu(mean_e) to nodes, then transform: n0 = (agg/degn) @ We0 + be0
    cudaMemsetAsync(aa, 0, (size_t)Nn * Dn * sizeof(float), 0);
    scatter_e2n_kernel<<<gInc, TB>>>(e, hidx, dege, pa, aa);
    sgemm128<<<gmN, TB>>>(aa, degn, 0, pa, We0, be0, nf, nullptr, Nn);

    // ================= layer 1 =================
    // t = prelu(n0) @ Wv1 + bv1
    sgemm128<<<gmN, TB>>>(nf, nullptr, 1, pa, Wv1, bv1, t, Nn ? nullptr : nullptr, Nn);
    cudaMemsetAsync(e, 0, (size_t)ETn * Dn * sizeof(float), 0);
    scatter_v2e_kernel<<<gInc, TB>>>(t, hidx, e);
    // aggregate, then n1 = (agg/degn) @ We1 + be1 ; also write prelu(n1) to output
    cudaMemsetAsync(aa, 0, (size_t)Nn * Dn * sizeof(float), 0);
    scatter_e2n_kernel<<<gInc, TB>>>(e, hidx, dege, pa, aa);
    float* out = (float*)d_out;
    sgemm128<<<gmN, TB>>>(aa, degn, 0, pa, We1, be1, nf, out, Nn);

    // e output: prelu(Eraw/deg)[:E]
    out_e_kernel<<<gE32, TB>>>(e, dege, pa, out + (size_t)Nn * Dn);

    // e2c: aggregate e -> components, then GEMM on C rows
    cudaMemsetAsync(cA, 0, (size_t)Cn * Dn * sizeof(float), 0);
    scatter_e2c_kernel<<<gE32, TB>>>(e, hc, hc + En, dege, pa, cA);
    sgemm128<<<gmC, TB>>>(cA, cce, 0, pa, Wec1, bec1, cEo, nullptr, Cn);

    // n2c: aggregate n1 -> components, then GEMM on C rows
    cudaMemsetAsync(cB, 0, (size_t)Cn * Dn * sizeof(float), 0);
    scatter_n2c_kernel<<<gN32, TB>>>(nf, nc, nc + Nn, cB);
    sgemm128<<<gmC, TB>>>(cB, ccn, 0, pa, Wnc1, bnc1, cNo, nullptr, Cn);

    // c output
    out_c_kernel<<<gC32, TB>>>(cEo, cNo, pa, out + (size_t)(Nn + En) * Dn);

    (void)in_sizes; (void)n_in; (void)out_size;
}